// round 12
// baseline (speedup 1.0000x reference)
#include <cuda_runtime.h>
#include <cuda_fp16.h>
#include <math.h>
#include <stdint.h>
#include <stddef.h>

#define Bv 1024
#define Tv 256
#define EH 256
#define DH 512
#define ZL 128
#define PTc 5
#define OUTC 123

// ---------------- device scratch ----------------
__device__ __half d_WhhFh[4*EH*EH];   // encoder recurrent, gate-interleaved, fp16
__device__ float  d_WihF[4*EH*PTc];
__device__ float  d_bF[4*EH];
__device__ __half d_WhhDh[4*DH*DH];   // decoder recurrent, interleaved, fp16
__device__ float  d_WihS[4*DH*PTc];
__device__ float  d_bDi[4*DH];
__device__ __half d_Wouth[128*DH];    // [n][k], rows >= OUTC zeroed
__device__ float  d_WvaeT[512*256];
__device__ float  d_bvae[2*ZL];
__device__ float  d_Wh0T[128*512];
__device__ float  d_WzT[128*2048];
__device__ __half d_hEh[2][Bv*EH];
__device__ float  d_hback[Bv*EH];
__device__ float  d_mups[Bv*2*ZL];
__device__ float  d_z[Bv*ZL];
__device__ __half d_hDh[2][Bv*DH];
__device__ float  d_zproj[Bv*4*DH];
__device__ float  d_qpart[Tv*16];
__device__ volatile unsigned g_flagsE[128];
__device__ volatile unsigned g_flagsD[136];

// ---------------- scalar helpers ----------------
__device__ __forceinline__ float sigf(float x) { return 1.f / (1.f + __expf(-x)); }
__device__ __forceinline__ float tanh_f(float x) {
    float ax = fabsf(x);
    float e = __expf(2.f * ax);
    float t = 1.f - 2.f / (e + 1.f);
    return copysignf(t, x);
}
__device__ __forceinline__ float tanha(float x) {
    float y; asm("tanh.approx.f32 %0, %1;" : "=f"(y) : "f"(x)); return y;
}
__device__ __forceinline__ float sigfast(float x) { return fmaf(tanha(0.5f * x), 0.5f, 0.5f); }
__device__ __forceinline__ float wsum32(float v) {
    #pragma unroll
    for (int o = 16; o; o >>= 1) v += __shfl_xor_sync(0xffffffffu, v, o);
    return v;
}
__device__ __forceinline__ float wmax32(float v) {
    #pragma unroll
    for (int o = 16; o; o >>= 1) v = fmaxf(v, __shfl_xor_sync(0xffffffffu, v, o));
    return v;
}
__device__ __forceinline__ void mma16(float c[4], unsigned a0, unsigned a1, unsigned a2,
                                      unsigned a3, unsigned b0, unsigned b1) {
    asm volatile(
        "mma.sync.aligned.m16n8k16.row.col.f32.f16.f16.f32 "
        "{%0,%1,%2,%3}, {%4,%5,%6,%7}, {%8,%9}, {%0,%1,%2,%3};"
        : "+f"(c[0]), "+f"(c[1]), "+f"(c[2]), "+f"(c[3])
        : "r"(a0), "r"(a1), "r"(a2), "r"(a3), "r"(b0), "r"(b1));
}
__device__ __forceinline__ unsigned ldcg(const __half* p) {
    unsigned v; asm volatile("ld.global.cg.b32 %0, [%1];" : "=r"(v) : "l"(p)); return v;
}

// group-local grid barrier
__device__ __forceinline__ void gsync_g(volatile unsigned* flags, int fidx,
                                        int base, int cnt, unsigned gen) {
    __threadfence();
    __syncthreads();
    if (threadIdx.x == 0) flags[fidx] = gen;
    if (threadIdx.x < 32) {
        for (int i = base + (int)threadIdx.x; i < base + cnt; i += 32)
            while (flags[i] < gen) { }
    }
    __threadfence();
    __syncthreads();
}

// ---------------- direct-LDG A fragments + resident-B MMA ----------------
template<int MT>
__device__ __forceinline__ void loadA_frag(const __half* __restrict__ A, int lda, int kb,
                                           int wrow, int g, int tq, unsigned (*af)[8]) {
    #pragma unroll
    for (int mi = 0; mi < MT; mi++) {
        const __half* r0 = A + (size_t)(wrow + mi * 16 + g) * lda + kb + 2 * tq;
        const __half* r8 = r0 + (size_t)8 * lda;
        af[mi][0] = ldcg(r0);       af[mi][1] = ldcg(r8);
        af[mi][2] = ldcg(r0 + 8);   af[mi][3] = ldcg(r8 + 8);
        af[mi][4] = ldcg(r0 + 16);  af[mi][5] = ldcg(r8 + 16);
        af[mi][6] = ldcg(r0 + 24);  af[mi][7] = ldcg(r8 + 24);
    }
}

template<int MT, int BSU>
__device__ __forceinline__ void chunk_mma(
    const unsigned (*a)[8], int i, const unsigned* __restrict__ BsU,
    int wn, int g, int tq, float c[MT][4][4])
{
    #pragma unroll
    for (int j = 0; j < 2; j++) {
        unsigned b[4][2];
        #pragma unroll
        for (int ni = 0; ni < 4; ni++) {
            int cb = (wn * 32 + ni * 8 + g) * BSU + i * 16 + j * 8 + tq;
            b[ni][0] = BsU[cb];
            b[ni][1] = BsU[cb + 4];
        }
        #pragma unroll
        for (int mi = 0; mi < MT; mi++)
            #pragma unroll
            for (int ni = 0; ni < 4; ni++)
                mma16(c[mi][ni], a[mi][4 * j], a[mi][4 * j + 1], a[mi][4 * j + 2],
                      a[mi][4 * j + 3], b[ni][0], b[ni][1]);
    }
}

// C[MT*32 x 128] += A[MT*32 x K] @ B^T; A via ld.global.cg, B resident in SMEM.
template<int MT, int BSU>
__device__ __forceinline__ void mma_ldg(
    const __half* __restrict__ A, int lda, int K,
    const unsigned* __restrict__ BsU, float c[MT][4][4])
{
    const int lane = threadIdx.x & 31, warp = threadIdx.x >> 5;
    const int wm = warp >> 2, wn = warp & 3;
    const int g = lane >> 2, tq = lane & 3;
    const int wrow = wm * (MT * 16);
    const int nch = K / 32;   // even (8 or 16)
    unsigned a0[MT][8], a1[MT][8];
    loadA_frag<MT>(A, lda, 0, wrow, g, tq, a0);
    loadA_frag<MT>(A, lda, 32, wrow, g, tq, a1);
    for (int i = 0; i < nch; i += 2) {
        chunk_mma<MT, BSU>(a0, i, BsU, wn, g, tq, c);
        if (i + 2 < nch) loadA_frag<MT>(A, lda, (i + 2) * 32, wrow, g, tq, a0);
        chunk_mma<MT, BSU>(a1, i + 1, BsU, wn, g, tq, c);
        if (i + 3 < nch) loadA_frag<MT>(A, lda, (i + 3) * 32, wrow, g, tq, a1);
    }
}

// ---------------- fused LSTM cell epilogue (c in regs; zS fp16 or bias fp32) -----------
template<int MT>
__device__ __forceinline__ void cell_epi(
    float c[MT][4][4], int row0, int col0, int H,
    const __half* zS, const float* bS, const float* w5S,
    const float* __restrict__ sPtr, int xt,
    __half* __restrict__ hnext, float* cst)
{
    const int tid = threadIdx.x, lane = tid & 31, warp = tid >> 5;
    const int wm = warp >> 2, wn = warp & 3, g = lane >> 2, q = lane & 3;
    const bool hi = (q & 1) != 0;
    #pragma unroll
    for (int mi = 0; mi < MT; mi++) {
        int rowt = wm * (MT * 16) + mi * 16 + g + (hi ? 8 : 0);
        int row = row0 + rowt;
        float xr[5];
        if (xt < 0) { xr[0] = 0.f; xr[1] = 0.f; xr[2] = 1.f; xr[3] = 0.f; xr[4] = 0.f; }
        else {
            const float* xp = sPtr + ((size_t)row * Tv + xt) * PTc;
            #pragma unroll
            for (int k = 0; k < 5; k++) xr[k] = xp[k];
        }
        #pragma unroll
        for (int ni = 0; ni < 4; ni++) {
            float d0 = __shfl_xor_sync(0xffffffffu, c[mi][ni][0], 1);
            float d1 = __shfl_xor_sync(0xffffffffu, c[mi][ni][1], 1);
            float d2 = __shfl_xor_sync(0xffffffffu, c[mi][ni][2], 1);
            float d3 = __shfl_xor_sync(0xffffffffu, c[mi][ni][3], 1);
            float gi, gf, gg, go;
            if (!hi) { gi = c[mi][ni][0]; gf = c[mi][ni][1]; gg = d0; go = d1; }
            else     { gi = d2;           gf = d3;           gg = c[mi][ni][2]; go = c[mi][ni][3]; }
            int lc = wn * 32 + ni * 8 + (q >> 1) * 4;
            if (zS) {
                const __half2* zp = (const __half2*)(zS + rowt * 132 + lc);
                float2 z0 = __half22float2(zp[0]);
                float2 z1 = __half22float2(zp[1]);
                gi += z0.x; gf += z0.y; gg += z1.x; go += z1.y;
            } else {
                gi += bS[lc]; gf += bS[lc + 1]; gg += bS[lc + 2]; go += bS[lc + 3];
            }
            const float* w5 = w5S + lc * 5;
            #pragma unroll
            for (int k = 0; k < 5; k++) {
                gi += xr[k] * w5[k];
                gf += xr[k] * w5[5 + k];
                gg += xr[k] * w5[10 + k];
                go += xr[k] * w5[15 + k];
            }
            float cc = sigfast(gf) * cst[mi * 4 + ni] + sigfast(gi) * tanha(gg);
            cst[mi * 4 + ni] = cc;
            hnext[(size_t)row * H + ((col0 + lc) >> 2)] = __float2half(sigfast(go) * tanha(cc));
        }
    }
}

// ---------------- y epilogue (eq left unnormalized; qkfinal normalizes) ----------------
__device__ __forceinline__ void y_epi(
    float c[4][4][4], int row0, int tstep,
    const float* __restrict__ bout, float* __restrict__ out,
    float* ys /*64*128*/, float* wsum)
{
    const int tid = threadIdx.x, lane = tid & 31, warp = tid >> 5;
    const int wm = warp >> 2, wn = warp & 3, g = lane >> 2, q = lane & 3;
    for (int half = 0; half < 2; half++) {
        __syncthreads();
        if (wm == half) {
            #pragma unroll
            for (int mi = 0; mi < 4; mi++)
                #pragma unroll
                for (int ni = 0; ni < 4; ni++)
                    #pragma unroll
                    for (int cid = 0; cid < 4; cid++) {
                        int col = wn * 32 + ni * 8 + 2 * q + (cid & 1);
                        if (col < OUTC) {
                            int r = mi * 16 + g + ((cid >= 2) ? 8 : 0);
                            ys[r * 128 + col] = c[mi][ni][cid] + bout[col];
                        }
                    }
        }
        __syncthreads();
        float qacc = 0.f;
        for (int rr = 0; rr < 8; rr++) {
            int r = warp * 8 + rr;
            int brow = row0 + half * 64 + r;
            float* orow = out + ((size_t)tstep * Bv + brow) * OUTC;
            float v = (lane < 20) ? ys[r * 128 + lane * 6] : -3.0e38f;
            float m = wmax32(v);
            float e = (lane < 20) ? __expf(v - m) : 0.f;
            float ss = wsum32(e);
            if (lane < 20) {
                orow[lane]       = e / ss;
                orow[20 + lane]  = ys[r * 128 + lane * 6 + 1];
                orow[40 + lane]  = ys[r * 128 + lane * 6 + 2];
                orow[60 + lane]  = __expf(ys[r * 128 + lane * 6 + 3]);
                orow[80 + lane]  = __expf(ys[r * 128 + lane * 6 + 4]);
                orow[100 + lane] = tanh_f(ys[r * 128 + lane * 6 + 5]);
            } else if (lane < 23) {
                float eq = __expf(ys[r * 128 + 120 + lane - 20]);
                orow[120 + lane - 20] = eq;
                qacc += eq;
            }
        }
        float qs = wsum32(qacc);
        if (lane == 0) wsum[warp] = qs;
        __syncthreads();
        if (tid == 0) {
            float tot = 0.f;
            #pragma unroll
            for (int i = 0; i < 8; i++) tot += wsum[i];
            d_qpart[tstep * 16 + ((row0 + half * 64) >> 6)] = tot;
        }
        __syncthreads();
    }
}

// final qk normalization (one block per timestep)
__global__ void qkfinal(float* __restrict__ out) {
    int t = blockIdx.x;
    __shared__ float sinv;
    if (threadIdx.x == 0) {
        float tot = 0.f;
        #pragma unroll
        for (int i = 0; i < 16; i++) tot += d_qpart[t * 16 + i];
        sinv = 1.f / tot;
    }
    __syncthreads();
    float inv = sinv;
    for (int idx = threadIdx.x; idx < Bv * 3; idx += 256)
        out[((size_t)t * Bv + (idx / 3)) * OUTC + 120 + (idx % 3)] *= inv;
}

// ---------------- kernels ----------------
__global__ void reset_k() {
    int i = threadIdx.x;
    if (i < 128) g_flagsE[i] = 0;
    if (i < 136) g_flagsD[i] = 0;
}

__global__ void prep_k(const float* __restrict__ eWihF, const float* __restrict__ eWhhF,
                       const float* __restrict__ ebF,  const float* __restrict__ eWihB,
                       const float* __restrict__ ebB,  const float* __restrict__ dWih,
                       const float* __restrict__ dWhh, const float* __restrict__ db,
                       const float* __restrict__ Wmu,  const float* __restrict__ bmu,
                       const float* __restrict__ Wsig, const float* __restrict__ bsig,
                       const float* __restrict__ Wh0,  const float* __restrict__ Wout,
                       const float* __restrict__ s)
{
    int gt = blockIdx.x * blockDim.x + threadIdx.x;
    int gs = gridDim.x * blockDim.x;
    for (int i = gt; i < 4 * DH * DH; i += gs) {
        int n = i / DH, k = i - n * DH, j = n >> 2, g4 = n & 3;
        d_WhhDh[i] = __float2half(dWhh[(size_t)(g4 * DH + j) * DH + k]);
    }
    for (int i = gt; i < 4 * DH * PTc; i += gs) {
        int n = i / PTc, k = i - n * PTc, j = n >> 2, g4 = n & 3;
        d_WihS[i] = dWih[(size_t)(g4 * DH + j) * (PTc + ZL) + k];
    }
    for (int i = gt; i < ZL * 4 * DH; i += gs) {
        int k = i / (4 * DH), n = i - k * (4 * DH), j = n >> 2, g4 = n & 3;
        d_WzT[i] = dWih[(size_t)(g4 * DH + j) * (PTc + ZL) + PTc + k];
    }
    for (int i = gt; i < 4 * DH; i += gs) {
        int j = i >> 2, g4 = i & 3;
        d_bDi[i] = db[g4 * DH + j];
    }
    for (int i = gt; i < 4 * EH * EH; i += gs) {
        int n = i / EH, k = i - n * EH, j = n >> 2, g4 = n & 3;
        d_WhhFh[i] = __float2half(eWhhF[(size_t)(g4 * EH + j) * EH + k]);
    }
    for (int i = gt; i < 4 * EH * PTc; i += gs) {
        int n = i / PTc, k = i - n * PTc, j = n >> 2, g4 = n & 3;
        d_WihF[i] = eWihF[(g4 * EH + j) * PTc + k];
    }
    for (int i = gt; i < 4 * EH; i += gs) {
        int j = i >> 2, g4 = i & 3;
        d_bF[i] = ebF[g4 * EH + j];
    }
    for (int i = gt; i < 128 * DH; i += gs) {
        int n = i / DH, k = i - n * DH;
        d_Wouth[i] = __float2half((n < OUTC) ? Wout[(size_t)n * DH + k] : 0.f);
    }
    for (int i = gt; i < 512 * 256; i += gs) {
        int k = i >> 8, j = i & 255;
        d_WvaeT[i] = (j < ZL) ? Wmu[(size_t)j * 512 + k] : Wsig[(size_t)(j - ZL) * 512 + k];
    }
    for (int i = gt; i < 2 * ZL; i += gs) d_bvae[i] = (i < ZL) ? bmu[i] : bsig[i - ZL];
    for (int i = gt; i < ZL * DH; i += gs) {
        int k = i / DH, n = i - k * DH;
        d_Wh0T[i] = Wh0[(size_t)n * ZL + k];
    }
    for (int i = gt; i < Bv * EH; i += gs) d_hEh[0][i] = __float2half(0.f);
    for (int i = gt; i < Bv * EH; i += gs) {   // backward enc LSTM = 1 step
        int b = i / EH, j = i - (i / EH) * EH;
        const float* xp = s + ((size_t)b * Tv + (Tv - 1)) * PTc;
        float gv[4];
        #pragma unroll
        for (int g = 0; g < 4; g++) {
            float a = ebB[g * EH + j];
            #pragma unroll
            for (int k = 0; k < 5; k++) a += eWihB[(size_t)(g * EH + j) * PTc + k] * xp[k];
            gv[g] = a;
        }
        float c = sigf(gv[0]) * tanh_f(gv[2]);
        d_hback[i] = sigf(gv[3]) * tanh_f(c);
    }
}

// encoder: 128 blocks = 16 row groups(64 rows) x 8 col tiles(128); B resident; A via LDG
#define ENC_SMB (67584 + 2560 + 512)
__global__ void __launch_bounds__(256, 1) enc_kernel(const float* __restrict__ s) {
    extern __shared__ __align__(16) char dsm[];
    const int tid = threadIdx.x, bid = blockIdx.x;
    int row0 = (bid >> 3) * 64, col0 = (bid & 7) * 128;
    int rg = bid >> 3;
    unsigned* Bres = (unsigned*)dsm;
    float* w5S = (float*)(dsm + 67584);
    float* bS  = (float*)(dsm + 67584 + 2560);
    const unsigned* Wu = (const unsigned*)d_WhhFh;
    for (int i = tid; i < 128 * 128; i += 256)
        Bres[(i >> 7) * 132 + (i & 127)] = Wu[(size_t)(col0 + (i >> 7)) * 128 + (i & 127)];
    for (int i = tid; i < 128 * 5; i += 256) w5S[i] = d_WihF[(size_t)col0 * 5 + i];
    for (int i = tid; i < 128; i += 256) bS[i] = d_bF[col0 + i];
    __syncthreads();
    float cst[8];
    #pragma unroll
    for (int i = 0; i < 8; i++) cst[i] = 0.f;
    for (int t = 0; t < Tv; t++) {
        const __half* hprev = d_hEh[t & 1];
        __half* hnext = d_hEh[(t + 1) & 1];
        float c[2][4][4] = {};
        mma_ldg<2, 132>(hprev + (size_t)row0 * EH, EH, EH, Bres, c);
        cell_epi<2>(c, row0, col0, EH, nullptr, bS, w5S, s, t, hnext, cst);
        gsync_g(g_flagsE, bid, rg * 8, 8, t + 1);
    }
}

__global__ void vae1_k() {
    __shared__ float h[4][512];
    int b0 = blockIdx.x * 4, tid = threadIdx.x;
    for (int i = tid; i < 4 * 512; i += 256) {
        int r = i >> 9, k = i & 511;
        h[r][k] = (k < 256) ? __half2float(d_hEh[0][(size_t)(b0 + r) * 256 + k])
                            : d_hback[(size_t)(b0 + r) * 256 + k - 256];
    }
    __syncthreads();
    float acc[4];
    #pragma unroll
    for (int r = 0; r < 4; r++) acc[r] = d_bvae[tid];
    for (int k = 0; k < 512; k++) {
        float w = d_WvaeT[k * 256 + tid];
        #pragma unroll
        for (int r = 0; r < 4; r++) acc[r] += h[r][k] * w;
    }
    #pragma unroll
    for (int r = 0; r < 4; r++) d_mups[(size_t)(b0 + r) * 256 + tid] = acc[r];
}

__global__ void zk(const float* __restrict__ eps) {
    int i = blockIdx.x * blockDim.x + threadIdx.x;
    if (i < Bv * ZL) {
        int b = i >> 7, j = i & 127;
        d_z[i] = d_mups[(size_t)b * 256 + j]
               + __expf(0.5f * d_mups[(size_t)b * 256 + 128 + j]) * eps[i];
    }
}

__global__ void vae2a_k(const float* __restrict__ bh0) {
    __shared__ float z4[4][128];
    int b0 = blockIdx.x * 4, tid = threadIdx.x;
    for (int i = tid; i < 4 * 128; i += 512) z4[i >> 7][i & 127] = d_z[(size_t)b0 * 128 + i];
    __syncthreads();
    float acc[4];
    #pragma unroll
    for (int r = 0; r < 4; r++) acc[r] = bh0[tid];
    for (int k = 0; k < 128; k++) {
        float w = d_Wh0T[k * 512 + tid];
        #pragma unroll
        for (int r = 0; r < 4; r++) acc[r] += z4[r][k] * w;
    }
    #pragma unroll
    for (int r = 0; r < 4; r++)
        d_hDh[0][(size_t)(b0 + r) * 512 + tid] = __float2half(tanh_f(acc[r]));
}

__global__ void vae2b_k() {
    __shared__ float z2[2][128];
    int b0 = blockIdx.x * 2, tid = threadIdx.x;
    for (int i = tid; i < 2 * 128; i += 256) z2[i >> 7][i & 127] = d_z[(size_t)b0 * 128 + i];
    __syncthreads();
    float acc[16];
    #pragma unroll
    for (int i = 0; i < 16; i++) acc[i] = 0.f;
    for (int k = 0; k < 128; k++) {
        float z0 = z2[0][k], z1 = z2[1][k];
        #pragma unroll
        for (int m = 0; m < 8; m++) {
            float w = d_WzT[(size_t)k * 2048 + tid + 256 * m];
            acc[m] += z0 * w;
            acc[8 + m] += z1 * w;
        }
    }
    #pragma unroll
    for (int m = 0; m < 8; m++) {
        float bb = d_bDi[tid + 256 * m];
        d_zproj[(size_t)b0 * 2048 + tid + 256 * m] = acc[m] + bb;
        d_zproj[(size_t)(b0 + 1) * 2048 + tid + 256 * m] = acc[8 + m] + bb;
    }
}

// decoder: 136 blocks = 8 row groups x (16 gate tiles + 1 y tile)
// SMEM: Bres/WoutRes [128*260]u32 @0 (133120) | zS half[128*132] / ys @133120 (33792)
//       | w5S @166912 (2560) | wsum @169472 (64)
#define DEC_SMB (133120 + 33792 + 2560 + 64)
__global__ void __launch_bounds__(256, 1) dec_kernel(const float* __restrict__ s,
    const float* __restrict__ bout, float* __restrict__ out)
{
    extern __shared__ __align__(16) char dsm[];
    const int tid = threadIdx.x, bid = blockIdx.x;
    unsigned* Bres = (unsigned*)dsm;
    float* wsum = (float*)(dsm + 133120 + 33792 + 2560);
    if (bid < 128) {
        int rg = bid >> 4;
        int row0 = rg * 128, col0 = (bid & 15) * 128;
        int fidx = rg * 17 + (bid & 15);
        __half* zS = (__half*)(dsm + 133120);
        float* w5S = (float*)(dsm + 133120 + 33792);
        const unsigned* Wu = (const unsigned*)d_WhhDh;
        for (int i = tid; i < 128 * 256; i += 256)
            Bres[(i >> 8) * 260 + (i & 255)] = Wu[(size_t)(col0 + (i >> 8)) * 256 + (i & 255)];
        for (int i = tid; i < 128 * 128; i += 256) {
            int r = i >> 7, cc = i & 127;
            zS[r * 132 + cc] = __float2half(d_zproj[(size_t)(row0 + r) * 2048 + col0 + cc]);
        }
        for (int i = tid; i < 128 * 5; i += 256) w5S[i] = d_WihS[(size_t)col0 * 5 + i];
        __syncthreads();
        float cst[16];
        #pragma unroll
        for (int i = 0; i < 16; i++) cst[i] = 0.f;
        for (int t = 0; t < Tv; t++) {
            const __half* hprev = d_hDh[t & 1];
            __half* hnext = d_hDh[(t + 1) & 1];
            float c[4][4][4] = {};
            mma_ldg<4, 260>(hprev + (size_t)row0 * DH, DH, DH, Bres, c);
            cell_epi<4>(c, row0, col0, DH, zS, nullptr, w5S, s, t - 1, hnext, cst);
            gsync_g(g_flagsD, fidx, rg * 17, 17, t + 1);
        }
    } else {
        int rg = bid - 128;
        int row0 = rg * 128;
        int fidx = rg * 17 + 16;
        float* ys = (float*)(dsm + 133120);
        const unsigned* Wu = (const unsigned*)d_Wouth;
        for (int i = tid; i < 128 * 256; i += 256)
            Bres[(i >> 8) * 260 + (i & 255)] = Wu[(size_t)(i >> 8) * 256 + (i & 255)];
        __syncthreads();
        for (int t = 0; t < Tv; t++) {
            const __half* hprev = d_hDh[t & 1];
            if (t >= 1) {
                float c[4][4][4] = {};
                mma_ldg<4, 260>(hprev + (size_t)row0 * DH, DH, DH, Bres, c);
                y_epi(c, row0, t - 1, bout, out, ys, wsum);
            }
            gsync_g(g_flagsD, fidx, rg * 17, 17, t + 1);
        }
        float c[4][4][4] = {};
        mma_ldg<4, 260>(d_hDh[0] + (size_t)row0 * DH, DH, DH, Bres, c);
        y_epi(c, row0, 255, bout, out, ys, wsum);
    }
}

// ---------------- launch ----------------
extern "C" void kernel_launch(void* const* d_in, const int* in_sizes, int n_in,
                              void* d_out, int out_size)
{
    const float* s     = (const float*)d_in[0];
    const float* eps   = (const float*)d_in[1];
    const float* eWihF = (const float*)d_in[2];
    const float* eWhhF = (const float*)d_in[3];
    const float* ebF   = (const float*)d_in[4];
    const float* eWihB = (const float*)d_in[5];
    // d_in[6] = enc_Whh_b : unused (backward LSTM output only needs its first step)
    const float* ebB   = (const float*)d_in[7];
    const float* Wmu   = (const float*)d_in[8];
    const float* bmu   = (const float*)d_in[9];
    const float* Wsig  = (const float*)d_in[10];
    const float* bsig  = (const float*)d_in[11];
    const float* Wh0   = (const float*)d_in[12];
    const float* bh0   = (const float*)d_in[13];
    const float* dWih  = (const float*)d_in[14];
    const float* dWhh  = (const float*)d_in[15];
    const float* db    = (const float*)d_in[16];
    const float* Wout  = (const float*)d_in[17];
    const float* bout  = (const float*)d_in[18];
    float* out = (float*)d_out;

    static int inited = 0;
    if (!inited) {
        cudaFuncSetAttribute(enc_kernel, cudaFuncAttributeMaxDynamicSharedMemorySize, ENC_SMB);
        cudaFuncSetAttribute(dec_kernel, cudaFuncAttributeMaxDynamicSharedMemorySize, DEC_SMB);
        inited = 1;
    }

    reset_k<<<1, 256>>>();
    prep_k<<<2048, 256>>>(eWihF, eWhhF, ebF, eWihB, ebB, dWih, dWhh, db,
                          Wmu, bmu, Wsig, bsig, Wh0, Wout, s);
    enc_kernel<<<128, 256, ENC_SMB>>>(s);
    vae1_k<<<256, 256>>>();
    zk<<<(Bv * ZL + 255) / 256, 256>>>(eps);
    vae2a_k<<<256, 512>>>(bh0);
    vae2b_k<<<512, 256>>>();
    dec_kernel<<<136, 256, DEC_SMB>>>(s, bout, out);
    qkfinal<<<Tv, 256>>>(out);
}

// round 13
// speedup vs baseline: 1.5470x; 1.5470x over previous
#include <cuda_runtime.h>
#include <cuda_fp16.h>
#include <math.h>
#include <stdint.h>
#include <stddef.h>

#define Bv 1024
#define Tv 256
#define EH 256
#define DH 512
#define ZL 128
#define PTc 5
#define OUTC 123

// ---------------- device scratch ----------------
__device__ __half d_WhhFh[4*EH*EH];   // encoder recurrent, gate-interleaved, fp16
__device__ float  d_WihF[4*EH*PTc];
__device__ float  d_bF[4*EH];
__device__ __half d_WhhDh[4*DH*DH];   // decoder recurrent, interleaved, fp16
__device__ float  d_WihS[4*DH*PTc];
__device__ float  d_bDi[4*DH];
__device__ __half d_Wouth[128*DH];    // [n][k], rows >= OUTC zeroed
__device__ float  d_WvaeT[512*256];
__device__ float  d_bvae[2*ZL];
__device__ float  d_Wh0T[128*512];
__device__ float  d_WzT[128*2048];
__device__ __half d_hEh[2][Bv*EH];
__device__ float  d_hback[Bv*EH];
__device__ float  d_mups[Bv*2*ZL];
__device__ float  d_z[Bv*ZL];
__device__ __half d_hDh[2][Bv*DH];
__device__ float  d_zproj[Bv*4*DH];
__device__ float  d_qpart[Tv*16];
__device__ volatile unsigned g_flagsE[128];
__device__ volatile unsigned g_flagsD[136];

// ---------------- scalar helpers ----------------
__device__ __forceinline__ float sigf(float x) { return 1.f / (1.f + __expf(-x)); }
__device__ __forceinline__ float tanh_f(float x) {
    float ax = fabsf(x);
    float e = __expf(2.f * ax);
    float t = 1.f - 2.f / (e + 1.f);
    return copysignf(t, x);
}
__device__ __forceinline__ float tanha(float x) {
    float y; asm("tanh.approx.f32 %0, %1;" : "=f"(y) : "f"(x)); return y;
}
__device__ __forceinline__ float sigfast(float x) { return fmaf(tanha(0.5f * x), 0.5f, 0.5f); }
__device__ __forceinline__ float wsum32(float v) {
    #pragma unroll
    for (int o = 16; o; o >>= 1) v += __shfl_xor_sync(0xffffffffu, v, o);
    return v;
}
__device__ __forceinline__ float wmax32(float v) {
    #pragma unroll
    for (int o = 16; o; o >>= 1) v = fmaxf(v, __shfl_xor_sync(0xffffffffu, v, o));
    return v;
}
__device__ __forceinline__ void mma16(float c[4], unsigned a0, unsigned a1, unsigned a2,
                                      unsigned a3, unsigned b0, unsigned b1) {
    asm volatile(
        "mma.sync.aligned.m16n8k16.row.col.f32.f16.f16.f32 "
        "{%0,%1,%2,%3}, {%4,%5,%6,%7}, {%8,%9}, {%0,%1,%2,%3};"
        : "+f"(c[0]), "+f"(c[1]), "+f"(c[2]), "+f"(c[3])
        : "r"(a0), "r"(a1), "r"(a2), "r"(a3), "r"(b0), "r"(b1));
}

// group-local grid barrier
__device__ __forceinline__ void gsync_g(volatile unsigned* flags, int fidx,
                                        int base, int cnt, unsigned gen) {
    __threadfence();
    __syncthreads();
    if (threadIdx.x == 0) flags[fidx] = gen;
    if (threadIdx.x < 32) {
        for (int i = base + (int)threadIdx.x; i < base + cnt; i += 32)
            while (flags[i] < gen) { }
    }
    __threadfence();
    __syncthreads();
}

// ---------------- cp.async ----------------
__device__ __forceinline__ uint32_t s2u(const void* p) { return (uint32_t)__cvta_generic_to_shared(p); }
__device__ __forceinline__ void cp16(uint32_t d, const void* s) {
    asm volatile("cp.async.cg.shared.global [%0], [%1], 16;" :: "r"(d), "l"(s));
}
__device__ __forceinline__ void cp_commit() { asm volatile("cp.async.commit_group;" ::: "memory"); }
template<int N> __device__ __forceinline__ void cp_wait() {
    asm volatile("cp.async.wait_group %0;" :: "n"(N) : "memory");
}

// ---- A-only chunk stage (32-K, stride 40 halves), 256 threads ----
template<int MT>
__device__ __forceinline__ void issueA(const __half* __restrict__ A, int lda,
                                       __half* st, int kb) {
    const int TOT = MT * 32 * 4;
    const int tid = threadIdx.x;
    #pragma unroll
    for (int it = 0; it < TOT / 256; it++) {
        int idx = tid + it * 256;
        int row = idx >> 2, seg = idx & 3;
        cp16(s2u(st + row * 40 + seg * 8), A + (size_t)row * lda + kb + seg * 8);
    }
}

// C[MT*32 x 128] += A @ B^T with B RESIDENT in SMEM (stride BSU u32 per row).
template<int MT, int BSU>
__device__ __forceinline__ void mma_pipeR(
    const __half* __restrict__ A, int lda, int K,
    const unsigned* __restrict__ BsU, __half* stgA, float c[MT][4][4])
{
    const int STGH = MT * 32 * 40;
    const int tid = threadIdx.x, lane = tid & 31, warp = tid >> 5;
    const int wm = warp >> 2, wn = warp & 3;
    const int g = lane >> 2, tq = lane & 3;
    const int wrow = wm * (MT * 16);
    const int nch = K / 32;

    issueA<MT>(A, lda, stgA, 0); cp_commit();
    if (nch > 1) issueA<MT>(A, lda, stgA + STGH, 32);
    cp_commit();
    if (nch > 2) issueA<MT>(A, lda, stgA + 2 * STGH, 64);
    cp_commit();

    for (int i = 0; i < nch; i++) {
        if (i + 3 < nch) issueA<MT>(A, lda, stgA + ((i + 3) & 3) * STGH, (i + 3) * 32);
        cp_commit();
        cp_wait<3>();
        __syncthreads();
        const unsigned* AsU = (const unsigned*)(stgA + (i & 3) * STGH);
        #pragma unroll
        for (int j = 0; j < 2; j++) {
            unsigned a[MT][4];
            #pragma unroll
            for (int mi = 0; mi < MT; mi++) {
                int rb = (wrow + mi * 16 + g) * 20 + j * 8 + tq;
                a[mi][0] = AsU[rb];
                a[mi][1] = AsU[rb + 8 * 20];
                a[mi][2] = AsU[rb + 4];
                a[mi][3] = AsU[rb + 8 * 20 + 4];
            }
            unsigned b[4][2];
            #pragma unroll
            for (int ni = 0; ni < 4; ni++) {
                int cb = (wn * 32 + ni * 8 + g) * BSU + i * 16 + j * 8 + tq;
                b[ni][0] = BsU[cb];
                b[ni][1] = BsU[cb + 4];
            }
            #pragma unroll
            for (int mi = 0; mi < MT; mi++)
                #pragma unroll
                for (int ni = 0; ni < 4; ni++)
                    mma16(c[mi][ni], a[mi][0], a[mi][1], a[mi][2], a[mi][3], b[ni][0], b[ni][1]);
        }
        __syncthreads();
    }
}

// ---------------- fused LSTM cell epilogue (c in regs; zS fp16 or bias fp32) -----------
template<int MT>
__device__ __forceinline__ void cell_epi(
    float c[MT][4][4], int row0, int col0, int H,
    const __half* zS, const float* bS, const float* w5S,
    const float* __restrict__ sPtr, int xt,
    __half* __restrict__ hnext, float* cst)
{
    const int tid = threadIdx.x, lane = tid & 31, warp = tid >> 5;
    const int wm = warp >> 2, wn = warp & 3, g = lane >> 2, q = lane & 3;
    const bool hi = (q & 1) != 0;
    #pragma unroll
    for (int mi = 0; mi < MT; mi++) {
        int rowt = wm * (MT * 16) + mi * 16 + g + (hi ? 8 : 0);
        int row = row0 + rowt;
        float xr[5];
        if (xt < 0) { xr[0] = 0.f; xr[1] = 0.f; xr[2] = 1.f; xr[3] = 0.f; xr[4] = 0.f; }
        else {
            const float* xp = sPtr + ((size_t)row * Tv + xt) * PTc;
            #pragma unroll
            for (int k = 0; k < 5; k++) xr[k] = xp[k];
        }
        #pragma unroll
        for (int ni = 0; ni < 4; ni++) {
            float d0 = __shfl_xor_sync(0xffffffffu, c[mi][ni][0], 1);
            float d1 = __shfl_xor_sync(0xffffffffu, c[mi][ni][1], 1);
            float d2 = __shfl_xor_sync(0xffffffffu, c[mi][ni][2], 1);
            float d3 = __shfl_xor_sync(0xffffffffu, c[mi][ni][3], 1);
            float gi, gf, gg, go;
            if (!hi) { gi = c[mi][ni][0]; gf = c[mi][ni][1]; gg = d0; go = d1; }
            else     { gi = d2;           gf = d3;           gg = c[mi][ni][2]; go = c[mi][ni][3]; }
            int lc = wn * 32 + ni * 8 + (q >> 1) * 4;
            if (zS) {
                const __half2* zp = (const __half2*)(zS + rowt * 132 + lc);
                float2 z0 = __half22float2(zp[0]);
                float2 z1 = __half22float2(zp[1]);
                gi += z0.x; gf += z0.y; gg += z1.x; go += z1.y;
            } else {
                gi += bS[lc]; gf += bS[lc + 1]; gg += bS[lc + 2]; go += bS[lc + 3];
            }
            const float* w5 = w5S + lc * 5;
            #pragma unroll
            for (int k = 0; k < 5; k++) {
                gi += xr[k] * w5[k];
                gf += xr[k] * w5[5 + k];
                gg += xr[k] * w5[10 + k];
                go += xr[k] * w5[15 + k];
            }
            float cc = sigfast(gf) * cst[mi * 4 + ni] + sigfast(gi) * tanha(gg);
            cst[mi * 4 + ni] = cc;
            hnext[(size_t)row * H + ((col0 + lc) >> 2)] = __float2half(sigfast(go) * tanha(cc));
        }
    }
}

// ---------------- y epilogue (eq left unnormalized; qkfinal normalizes) ----------------
__device__ __forceinline__ void y_epi(
    float c[4][4][4], int row0, int tstep,
    const float* __restrict__ bout, float* __restrict__ out,
    float* ys /*64*128*/, float* wsum)
{
    const int tid = threadIdx.x, lane = tid & 31, warp = tid >> 5;
    const int wm = warp >> 2, wn = warp & 3, g = lane >> 2, q = lane & 3;
    for (int half = 0; half < 2; half++) {
        if (wm == half) {
            #pragma unroll
            for (int mi = 0; mi < 4; mi++)
                #pragma unroll
                for (int ni = 0; ni < 4; ni++)
                    #pragma unroll
                    for (int cid = 0; cid < 4; cid++) {
                        int col = wn * 32 + ni * 8 + 2 * q + (cid & 1);
                        if (col < OUTC) {
                            int r = mi * 16 + g + ((cid >= 2) ? 8 : 0);
                            ys[r * 128 + col] = c[mi][ni][cid] + bout[col];
                        }
                    }
        }
        __syncthreads();
        float qacc = 0.f;
        for (int rr = 0; rr < 8; rr++) {
            int r = warp * 8 + rr;
            int brow = row0 + half * 64 + r;
            float* orow = out + ((size_t)tstep * Bv + brow) * OUTC;
            float v = (lane < 20) ? ys[r * 128 + lane * 6] : -3.0e38f;
            float m = wmax32(v);
            float e = (lane < 20) ? __expf(v - m) : 0.f;
            float ss = wsum32(e);
            if (lane < 20) {
                orow[lane]       = e / ss;
                orow[20 + lane]  = ys[r * 128 + lane * 6 + 1];
                orow[40 + lane]  = ys[r * 128 + lane * 6 + 2];
                orow[60 + lane]  = __expf(ys[r * 128 + lane * 6 + 3]);
                orow[80 + lane]  = __expf(ys[r * 128 + lane * 6 + 4]);
                orow[100 + lane] = tanh_f(ys[r * 128 + lane * 6 + 5]);
            } else if (lane < 23) {
                float eq = __expf(ys[r * 128 + 120 + lane - 20]);
                orow[120 + lane - 20] = eq;   // normalized by qkfinal
                qacc += eq;
            }
        }
        float qs = wsum32(qacc);
        if (lane == 0) wsum[warp] = qs;
        __syncthreads();
        if (tid == 0) {
            float tot = 0.f;
            #pragma unroll
            for (int i = 0; i < 8; i++) tot += wsum[i];
            d_qpart[tstep * 16 + ((row0 + half * 64) >> 6)] = tot;
        }
        __syncthreads();
    }
}

// final qk normalization (one block per timestep)
__global__ void qkfinal(float* __restrict__ out) {
    int t = blockIdx.x;
    __shared__ float sinv;
    if (threadIdx.x == 0) {
        float tot = 0.f;
        #pragma unroll
        for (int i = 0; i < 16; i++) tot += d_qpart[t * 16 + i];
        sinv = 1.f / tot;
    }
    __syncthreads();
    float inv = sinv;
    for (int idx = threadIdx.x; idx < Bv * 3; idx += 256)
        out[((size_t)t * Bv + (idx / 3)) * OUTC + 120 + (idx % 3)] *= inv;
}

// ---------------- kernels ----------------
__global__ void reset_k() {
    int i = threadIdx.x;
    if (i < 128) g_flagsE[i] = 0;
    if (i < 136) g_flagsD[i] = 0;
}

__global__ void prep_k(const float* __restrict__ eWihF, const float* __restrict__ eWhhF,
                       const float* __restrict__ ebF,  const float* __restrict__ eWihB,
                       const float* __restrict__ ebB,  const float* __restrict__ dWih,
                       const float* __restrict__ dWhh, const float* __restrict__ db,
                       const float* __restrict__ Wmu,  const float* __restrict__ bmu,
                       const float* __restrict__ Wsig, const float* __restrict__ bsig,
                       const float* __restrict__ Wh0,  const float* __restrict__ Wout,
                       const float* __restrict__ s)
{
    int gt = blockIdx.x * blockDim.x + threadIdx.x;
    int gs = gridDim.x * blockDim.x;
    for (int i = gt; i < 4 * DH * DH; i += gs) {
        int n = i / DH, k = i - n * DH, j = n >> 2, g4 = n & 3;
        d_WhhDh[i] = __float2half(dWhh[(size_t)(g4 * DH + j) * DH + k]);
    }
    for (int i = gt; i < 4 * DH * PTc; i += gs) {
        int n = i / PTc, k = i - n * PTc, j = n >> 2, g4 = n & 3;
        d_WihS[i] = dWih[(size_t)(g4 * DH + j) * (PTc + ZL) + k];
    }
    for (int i = gt; i < ZL * 4 * DH; i += gs) {
        int k = i / (4 * DH), n = i - k * (4 * DH), j = n >> 2, g4 = n & 3;
        d_WzT[i] = dWih[(size_t)(g4 * DH + j) * (PTc + ZL) + PTc + k];
    }
    for (int i = gt; i < 4 * DH; i += gs) {
        int j = i >> 2, g4 = i & 3;
        d_bDi[i] = db[g4 * DH + j];
    }
    for (int i = gt; i < 4 * EH * EH; i += gs) {
        int n = i / EH, k = i - n * EH, j = n >> 2, g4 = n & 3;
        d_WhhFh[i] = __float2half(eWhhF[(size_t)(g4 * EH + j) * EH + k]);
    }
    for (int i = gt; i < 4 * EH * PTc; i += gs) {
        int n = i / PTc, k = i - n * PTc, j = n >> 2, g4 = n & 3;
        d_WihF[i] = eWihF[(g4 * EH + j) * PTc + k];
    }
    for (int i = gt; i < 4 * EH; i += gs) {
        int j = i >> 2, g4 = i & 3;
        d_bF[i] = ebF[g4 * EH + j];
    }
    for (int i = gt; i < 128 * DH; i += gs) {
        int n = i / DH, k = i - n * DH;
        d_Wouth[i] = __float2half((n < OUTC) ? Wout[(size_t)n * DH + k] : 0.f);
    }
    for (int i = gt; i < 512 * 256; i += gs) {
        int k = i >> 8, j = i & 255;
        d_WvaeT[i] = (j < ZL) ? Wmu[(size_t)j * 512 + k] : Wsig[(size_t)(j - ZL) * 512 + k];
    }
    for (int i = gt; i < 2 * ZL; i += gs) d_bvae[i] = (i < ZL) ? bmu[i] : bsig[i - ZL];
    for (int i = gt; i < ZL * DH; i += gs) {
        int k = i / DH, n = i - k * DH;
        d_Wh0T[i] = Wh0[(size_t)n * ZL + k];
    }
    for (int i = gt; i < Bv * EH; i += gs) d_hEh[0][i] = __float2half(0.f);
    for (int i = gt; i < Bv * EH; i += gs) {   // backward enc LSTM = 1 step
        int b = i / EH, j = i - (i / EH) * EH;
        const float* xp = s + ((size_t)b * Tv + (Tv - 1)) * PTc;
        float gv[4];
        #pragma unroll
        for (int g = 0; g < 4; g++) {
            float a = ebB[g * EH + j];
            #pragma unroll
            for (int k = 0; k < 5; k++) a += eWihB[(size_t)(g * EH + j) * PTc + k] * xp[k];
            gv[g] = a;
        }
        float c = sigf(gv[0]) * tanh_f(gv[2]);
        d_hback[i] = sigf(gv[3]) * tanh_f(c);
    }
}

// encoder: 128 blocks = 16 row groups(64 rows) x 8 col tiles(128); B resident; K=256
#define ENC_SMB (67584 + 20480 + 2560 + 512)
__global__ void __launch_bounds__(256, 1) enc_kernel(const float* __restrict__ s) {
    extern __shared__ __align__(16) char dsm[];
    const int tid = threadIdx.x, bid = blockIdx.x;
    int row0 = (bid >> 3) * 64, col0 = (bid & 7) * 128;
    int rg = bid >> 3;
    unsigned* Bres = (unsigned*)dsm;
    __half* stgA = (__half*)(dsm + 67584);
    float* w5S = (float*)(dsm + 67584 + 20480);
    float* bS  = (float*)(dsm + 67584 + 20480 + 2560);
    const unsigned* Wu = (const unsigned*)d_WhhFh;
    for (int i = tid; i < 128 * 128; i += 256)
        Bres[(i >> 7) * 132 + (i & 127)] = Wu[(size_t)(col0 + (i >> 7)) * 128 + (i & 127)];
    for (int i = tid; i < 128 * 5; i += 256) w5S[i] = d_WihF[(size_t)col0 * 5 + i];
    for (int i = tid; i < 128; i += 256) bS[i] = d_bF[col0 + i];
    __syncthreads();
    float cst[8];
    #pragma unroll
    for (int i = 0; i < 8; i++) cst[i] = 0.f;
    for (int t = 0; t < Tv; t++) {
        const __half* hprev = d_hEh[t & 1];
        __half* hnext = d_hEh[(t + 1) & 1];
        float c[2][4][4] = {};
        mma_pipeR<2, 132>(hprev + (size_t)row0 * EH, EH, EH, Bres, stgA, c);
        cell_epi<2>(c, row0, col0, EH, nullptr, bS, w5S, s, t, hnext, cst);
        gsync_g(g_flagsE, bid, rg * 8, 8, t + 1);
    }
}

__global__ void vae1_k() {
    __shared__ float h[4][512];
    int b0 = blockIdx.x * 4, tid = threadIdx.x;
    for (int i = tid; i < 4 * 512; i += 256) {
        int r = i >> 9, k = i & 511;
        h[r][k] = (k < 256) ? __half2float(d_hEh[0][(size_t)(b0 + r) * 256 + k])
                            : d_hback[(size_t)(b0 + r) * 256 + k - 256];
    }
    __syncthreads();
    float acc[4];
    #pragma unroll
    for (int r = 0; r < 4; r++) acc[r] = d_bvae[tid];
    for (int k = 0; k < 512; k++) {
        float w = d_WvaeT[k * 256 + tid];
        #pragma unroll
        for (int r = 0; r < 4; r++) acc[r] += h[r][k] * w;
    }
    #pragma unroll
    for (int r = 0; r < 4; r++) d_mups[(size_t)(b0 + r) * 256 + tid] = acc[r];
}

__global__ void zk(const float* __restrict__ eps) {
    int i = blockIdx.x * blockDim.x + threadIdx.x;
    if (i < Bv * ZL) {
        int b = i >> 7, j = i & 127;
        d_z[i] = d_mups[(size_t)b * 256 + j]
               + __expf(0.5f * d_mups[(size_t)b * 256 + 128 + j]) * eps[i];
    }
}

__global__ void vae2a_k(const float* __restrict__ bh0) {
    __shared__ float z4[4][128];
    int b0 = blockIdx.x * 4, tid = threadIdx.x;
    for (int i = tid; i < 4 * 128; i += 512) z4[i >> 7][i & 127] = d_z[(size_t)b0 * 128 + i];
    __syncthreads();
    float acc[4];
    #pragma unroll
    for (int r = 0; r < 4; r++) acc[r] = bh0[tid];
    for (int k = 0; k < 128; k++) {
        float w = d_Wh0T[k * 512 + tid];
        #pragma unroll
        for (int r = 0; r < 4; r++) acc[r] += z4[r][k] * w;
    }
    #pragma unroll
    for (int r = 0; r < 4; r++)
        d_hDh[0][(size_t)(b0 + r) * 512 + tid] = __float2half(tanh_f(acc[r]));
}

__global__ void vae2b_k() {
    __shared__ float z2[2][128];
    int b0 = blockIdx.x * 2, tid = threadIdx.x;
    for (int i = tid; i < 2 * 128; i += 256) z2[i >> 7][i & 127] = d_z[(size_t)b0 * 128 + i];
    __syncthreads();
    float acc[16];
    #pragma unroll
    for (int i = 0; i < 16; i++) acc[i] = 0.f;
    for (int k = 0; k < 128; k++) {
        float z0 = z2[0][k], z1 = z2[1][k];
        #pragma unroll
        for (int m = 0; m < 8; m++) {
            float w = d_WzT[(size_t)k * 2048 + tid + 256 * m];
            acc[m] += z0 * w;
            acc[8 + m] += z1 * w;
        }
    }
    #pragma unroll
    for (int m = 0; m < 8; m++) {
        float bb = d_bDi[tid + 256 * m];
        d_zproj[(size_t)b0 * 2048 + tid + 256 * m] = acc[m] + bb;
        d_zproj[(size_t)(b0 + 1) * 2048 + tid + 256 * m] = acc[8 + m] + bb;
    }
}

// decoder: 136 blocks = 8 row groups x (16 gate tiles + 1 y tile); B resident everywhere
// gate SMEM: Bres[128*260]u32 @0 (133120) | stgA 4*128*40 halves @133120 (40960)
//            | zS half[128*132] @174080 (33792) | w5S @207872 (2560) | wsum @210432 (64)
// y SMEM:    WoutRes[128*260]u32 @0 | stgA @133120 | ys overlays stgA | wsum @210432
#define DEC_SMB (133120 + 40960 + 33792 + 2560 + 64)
__global__ void __launch_bounds__(256, 1) dec_kernel(const float* __restrict__ s,
    const float* __restrict__ bout, float* __restrict__ out)
{
    extern __shared__ __align__(16) char dsm[];
    const int tid = threadIdx.x, bid = blockIdx.x;
    unsigned* Bres = (unsigned*)dsm;
    __half* stgA = (__half*)(dsm + 133120);
    float* wsum = (float*)(dsm + 133120 + 40960 + 33792 + 2560);
    if (bid < 128) {
        int rg = bid >> 4;
        int row0 = rg * 128, col0 = (bid & 15) * 128;
        int fidx = rg * 17 + (bid & 15);
        __half* zS = (__half*)(dsm + 133120 + 40960);
        float* w5S = (float*)(dsm + 133120 + 40960 + 33792);
        const unsigned* Wu = (const unsigned*)d_WhhDh;
        for (int i = tid; i < 128 * 256; i += 256)
            Bres[(i >> 8) * 260 + (i & 255)] = Wu[(size_t)(col0 + (i >> 8)) * 256 + (i & 255)];
        for (int i = tid; i < 128 * 128; i += 256) {
            int r = i >> 7, cc = i & 127;
            zS[r * 132 + cc] = __float2half(d_zproj[(size_t)(row0 + r) * 2048 + col0 + cc]);
        }
        for (int i = tid; i < 128 * 5; i += 256) w5S[i] = d_WihS[(size_t)col0 * 5 + i];
        __syncthreads();
        float cst[16];
        #pragma unroll
        for (int i = 0; i < 16; i++) cst[i] = 0.f;
        for (int t = 0; t < Tv; t++) {
            const __half* hprev = d_hDh[t & 1];
            __half* hnext = d_hDh[(t + 1) & 1];
            float c[4][4][4] = {};
            mma_pipeR<4, 260>(hprev + (size_t)row0 * DH, DH, DH, Bres, stgA, c);
            cell_epi<4>(c, row0, col0, DH, zS, nullptr, w5S, s, t - 1, hnext, cst);
            gsync_g(g_flagsD, fidx, rg * 17, 17, t + 1);
        }
    } else {
        int rg = bid - 128;
        int row0 = rg * 128;
        int fidx = rg * 17 + 16;
        float* ys = (float*)(dsm + 133120);   // overlays stgA (drained by trailing sync)
        const unsigned* Wu = (const unsigned*)d_Wouth;
        for (int i = tid; i < 128 * 256; i += 256)
            Bres[(i >> 8) * 260 + (i & 255)] = Wu[(size_t)(i >> 8) * 256 + (i & 255)];
        __syncthreads();
        for (int t = 0; t < Tv; t++) {
            const __half* hprev = d_hDh[t & 1];
            if (t >= 1) {
                float c[4][4][4] = {};
                mma_pipeR<4, 260>(hprev + (size_t)row0 * DH, DH, DH, Bres, stgA, c);
                y_epi(c, row0, t - 1, bout, out, ys, wsum);
            }
            gsync_g(g_flagsD, fidx, rg * 17, 17, t + 1);
        }
        float c[4][4][4] = {};
        mma_pipeR<4, 260>(d_hDh[0] + (size_t)row0 * DH, DH, DH, Bres, stgA, c);
        y_epi(c, row0, 255, bout, out, ys, wsum);
    }
}

// ---------------- launch ----------------
extern "C" void kernel_launch(void* const* d_in, const int* in_sizes, int n_in,
                              void* d_out, int out_size)
{
    const float* s     = (const float*)d_in[0];
    const float* eps   = (const float*)d_in[1];
    const float* eWihF = (const float*)d_in[2];
    const float* eWhhF = (const float*)d_in[3];
    const float* ebF   = (const float*)d_in[4];
    const float* eWihB = (const float*)d_in[5];
    // d_in[6] = enc_Whh_b : unused (backward LSTM output only needs its first step)
    const float* ebB   = (const float*)d_in[7];
    const float* Wmu   = (const float*)d_in[8];
    const float* bmu   = (const float*)d_in[9];
    const float* Wsig  = (const float*)d_in[10];
    const float* bsig  = (const float*)d_in[11];
    const float* Wh0   = (const float*)d_in[12];
    const float* bh0   = (const float*)d_in[13];
    const float* dWih  = (const float*)d_in[14];
    const float* dWhh  = (const float*)d_in[15];
    const float* db    = (const float*)d_in[16];
    const float* Wout  = (const float*)d_in[17];
    const float* bout  = (const float*)d_in[18];
    float* out = (float*)d_out;

    static int inited = 0;
    if (!inited) {
        cudaFuncSetAttribute(enc_kernel, cudaFuncAttributeMaxDynamicSharedMemorySize, ENC_SMB);
        cudaFuncSetAttribute(dec_kernel, cudaFuncAttributeMaxDynamicSharedMemorySize, DEC_SMB);
        inited = 1;
    }

    reset_k<<<1, 256>>>();
    prep_k<<<2048, 256>>>(eWihF, eWhhF, ebF, eWihB, ebB, dWih, dWhh, db,
                          Wmu, bmu, Wsig, bsig, Wh0, Wout, s);
    enc_kernel<<<128, 256, ENC_SMB>>>(s);
    vae1_k<<<256, 256>>>();
    zk<<<(Bv * ZL + 255) / 256, 256>>>(eps);
    vae2a_k<<<256, 512>>>(bh0);
    vae2b_k<<<512, 256>>>();
    dec_kernel<<<136, 256, DEC_SMB>>>(s, bout, out);
    qkfinal<<<Tv, 256>>>(out);
}